// round 4
// baseline (speedup 1.0000x reference)
#include <cuda_runtime.h>
#include <math.h>

// ---------------------------------------------------------------------------
// Problem constants
// ---------------------------------------------------------------------------
#define Bb   2
#define Lseq 2048
#define Emb  1024
#define NH   16
#define DHd  64
#define FFd  4096
#define ROWS (Bb * Lseq)   // 4096
#define ATTN_SCALE 8.0f    // sqrt(DH) — reference MULTIPLIES by sqrt(dh)

// ---------------------------------------------------------------------------
// Scratch (no allocations allowed: __device__ globals)
// ---------------------------------------------------------------------------
__device__ float g_xn    [ROWS * Emb];
__device__ float g_q     [ROWS * Emb];
__device__ float g_k     [ROWS * Emb];
__device__ float g_v     [ROWS * Emb];
__device__ float g_ctx   [ROWS * Emb];
__device__ float g_hidden[ROWS * Emb];
__device__ float g_hn    [ROWS * Emb];
__device__ float g_up    [ROWS * FFd];

// ---------------------------------------------------------------------------
// LayerNorm: one block per row of 1024, 256 threads, float4
// ---------------------------------------------------------------------------
__global__ void __launch_bounds__(256)
layernorm_kernel(const float* __restrict__ x, const float* __restrict__ w,
                 const float* __restrict__ bsh, float* __restrict__ y)
{
    __shared__ float s1[256];
    __shared__ float s2[256];
    const int tid = threadIdx.x;
    const size_t row = blockIdx.x;
    const float4* xr = (const float4*)(x + row * Emb);
    float4 v = xr[tid];

    float a = v.x + v.y + v.z + v.w;
    float b = v.x * v.x + v.y * v.y + v.z * v.z + v.w * v.w;
    s1[tid] = a; s2[tid] = b;
    __syncthreads();
    #pragma unroll
    for (int st = 128; st > 0; st >>= 1) {
        if (tid < st) { s1[tid] += s1[tid + st]; s2[tid] += s2[tid + st]; }
        __syncthreads();
    }
    const float mu   = s1[0] * (1.0f / Emb);
    const float var  = s2[0] * (1.0f / Emb) - mu * mu;
    const float rstd = rsqrtf(var + 1e-5f);

    float4 wv = ((const float4*)w)[tid];
    float4 bv = ((const float4*)bsh)[tid];
    float4 o;
    o.x = (v.x - mu) * rstd * wv.x + bv.x;
    o.y = (v.y - mu) * rstd * wv.y + bv.y;
    o.z = (v.z - mu) * rstd * wv.z + bv.z;
    o.w = (v.w - mu) * rstd * wv.w + bv.w;
    ((float4*)(y + row * Emb))[tid] = o;
}

// ---------------------------------------------------------------------------
// SGEMM: C[M,N] = A[M,K] @ B[K,N] + bias (+res) (+GELU)
// 128x128x8 tile, 256 threads, 8x8 microtile, float4 everywhere.
// EPI: 0 = bias, 1 = bias + residual, 2 = bias + exact GELU
// ---------------------------------------------------------------------------
__device__ __forceinline__ float gelu_exact(float v) {
    return 0.5f * v * (1.0f + erff(v * 0.70710678118654752440f));
}

template <int EPI>
__global__ void __launch_bounds__(256)
sgemm_kernel(const float* __restrict__ A, const float* __restrict__ B,
             const float* __restrict__ bias, const float* __restrict__ res,
             float* __restrict__ C, int M, int N, int K)
{
    __shared__ float As[8][128];
    __shared__ float Bs[8][128];

    const int tid = threadIdx.x;
    const int bm = blockIdx.y * 128;
    const int bn = blockIdx.x * 128;
    const int tr = tid >> 4;          // 0..15
    const int tc = tid & 15;          // 0..15
    const int arow = tid >> 1;        // 0..127
    const int acol = (tid & 1) * 4;   // 0 or 4
    const int brow = tid >> 5;        // 0..7
    const int bcol = (tid & 31) * 4;  // 0..124

    const float* Ap = A + (size_t)(bm + arow) * K + acol;
    const float* Bp = B + (size_t)brow * N + bn + bcol;

    float acc[8][8];
    #pragma unroll
    for (int i = 0; i < 8; i++)
        #pragma unroll
        for (int j = 0; j < 8; j++) acc[i][j] = 0.0f;

    const int nk = K >> 3;
    for (int t = 0; t < nk; t++) {
        float4 av = *(const float4*)Ap;  Ap += 8;
        float4 bv = *(const float4*)Bp;  Bp += (size_t)8 * N;
        As[acol + 0][arow] = av.x;
        As[acol + 1][arow] = av.y;
        As[acol + 2][arow] = av.z;
        As[acol + 3][arow] = av.w;
        *(float4*)&Bs[brow][bcol] = bv;
        __syncthreads();

        #pragma unroll
        for (int k = 0; k < 8; k++) {
            float ra[8], rb[8];
            *(float4*)&ra[0] = *(const float4*)&As[k][tr * 8];
            *(float4*)&ra[4] = *(const float4*)&As[k][tr * 8 + 4];
            *(float4*)&rb[0] = *(const float4*)&Bs[k][tc * 8];
            *(float4*)&rb[4] = *(const float4*)&Bs[k][tc * 8 + 4];
            #pragma unroll
            for (int i = 0; i < 8; i++)
                #pragma unroll
                for (int j = 0; j < 8; j++)
                    acc[i][j] = fmaf(ra[i], rb[j], acc[i][j]);
        }
        __syncthreads();
    }

    #pragma unroll
    for (int i = 0; i < 8; i++) {
        const size_t row = (size_t)(bm + tr * 8 + i);
        #pragma unroll
        for (int j = 0; j < 8; j += 4) {
            const int col = bn + tc * 8 + j;
            float4 cv;
            cv.x = acc[i][j + 0] + bias[col + 0];
            cv.y = acc[i][j + 1] + bias[col + 1];
            cv.z = acc[i][j + 2] + bias[col + 2];
            cv.w = acc[i][j + 3] + bias[col + 3];
            if (EPI == 1) {
                float4 rv = *(const float4*)&res[row * N + col];
                cv.x += rv.x; cv.y += rv.y; cv.z += rv.z; cv.w += rv.w;
            }
            if (EPI == 2) {
                cv.x = gelu_exact(cv.x); cv.y = gelu_exact(cv.y);
                cv.z = gelu_exact(cv.z); cv.w = gelu_exact(cv.w);
            }
            *(float4*)&C[row * N + col] = cv;
        }
    }
}

// ---------------------------------------------------------------------------
// Flash attention (non-causal, full L). One CTA = 64 query rows of one (b,h).
// Tiles: Q 64x64 (d-major), K 64x64 (d-major), V 64x64 (m-major),
// S/P 64x64 stored m-major (sSt[m][i]) so both softmax and PV reads are
// conflict-free. Pitch 68 floats keeps float4 alignment + conflict-free reads.
// Dynamic smem: 4*64*68 + 3*64 floats = 70400 B.
// ---------------------------------------------------------------------------
#define FP 68  // smem pitch (floats)

__global__ void __launch_bounds__(256)
flash_attn_kernel(const float* __restrict__ Q, const float* __restrict__ K,
                  const float* __restrict__ V, float* __restrict__ Oo)
{
    extern __shared__ float sm[];
    float* sQt  = sm;                 // [64][FP]  sQt[d][i]
    float* sKt  = sm + 64 * FP;       // [64][FP]  sKt[d][j]
    float* sV   = sm + 2 * 64 * FP;   // [64][FP]  sV[m][d]
    float* sSt  = sm + 3 * 64 * FP;   // [64][FP]  sSt[m][i]  (S then P)
    float* mrow = sm + 4 * 64 * FP;   // [64]
    float* lrow = mrow + 64;          // [64]
    float* arow = lrow + 64;          // [64]

    const int tid = threadIdx.x;
    const int tr = tid >> 4;          // 0..15 -> rows 4*tr..+3
    const int tc = tid & 15;          // 0..15 -> cols 4*tc..+3
    const int bh = blockIdx.y;
    const int b = bh >> 4, h = bh & 15;
    const int r0 = blockIdx.x << 6;
    const size_t base = (size_t)b * Lseq * Emb + (size_t)h * DHd;

    // Load Q tile (transposed to d-major)
    for (int idx = tid; idx < 64 * 64; idx += 256) {
        const int i = idx >> 6, d = idx & 63;
        sQt[d * FP + i] = Q[base + (size_t)(r0 + i) * Emb + d];
    }
    if (tid < 64) { mrow[tid] = -1e30f; lrow[tid] = 0.0f; }
    __syncthreads();

    float o[4][4];
    #pragma unroll
    for (int i = 0; i < 4; i++)
        #pragma unroll
        for (int j = 0; j < 4; j++) o[i][j] = 0.0f;

    for (int kb = 0; kb < Lseq / 64; kb++) {
        const int c0 = kb << 6;
        for (int idx = tid; idx < 64 * 64; idx += 256) {
            const int j = idx >> 6, d = idx & 63;
            sKt[d * FP + j] = K[base + (size_t)(c0 + j) * Emb + d];
            sV [j * FP + d] = V[base + (size_t)(c0 + j) * Emb + d];
        }
        __syncthreads();

        // S = (Q K^T) * scale  — 4x4 microtile per thread
        float s[4][4];
        #pragma unroll
        for (int i = 0; i < 4; i++)
            #pragma unroll
            for (int j = 0; j < 4; j++) s[i][j] = 0.0f;

        #pragma unroll 8
        for (int d = 0; d < 64; d++) {
            float4 qf = *(const float4*)&sQt[d * FP + tr * 4];
            float4 kf = *(const float4*)&sKt[d * FP + tc * 4];
            float qa[4] = {qf.x, qf.y, qf.z, qf.w};
            float ka[4] = {kf.x, kf.y, kf.z, kf.w};
            #pragma unroll
            for (int i = 0; i < 4; i++)
                #pragma unroll
                for (int j = 0; j < 4; j++)
                    s[i][j] = fmaf(qa[i], ka[j], s[i][j]);
        }
        // write scaled S to sSt[m][i] (m = 4*tc+jj, i = 4*tr+ii)
        #pragma unroll
        for (int jj = 0; jj < 4; jj++) {
            float4 wv = make_float4(s[0][jj] * ATTN_SCALE, s[1][jj] * ATTN_SCALE,
                                    s[2][jj] * ATTN_SCALE, s[3][jj] * ATTN_SCALE);
            *(float4*)&sSt[(tc * 4 + jj) * FP + tr * 4] = wv;
        }
        __syncthreads();

        // online softmax: thread r (0..63) owns query row r
        if (tid < 64) {
            const int r = tid;
            float mx = mrow[r];
            #pragma unroll 8
            for (int m = 0; m < 64; m++) mx = fmaxf(mx, sSt[m * FP + r]);
            const float al = __expf(mrow[r] - mx);
            float sum = 0.0f;
            #pragma unroll 8
            for (int m = 0; m < 64; m++) {
                float p = __expf(sSt[m * FP + r] - mx);
                sSt[m * FP + r] = p;
                sum += p;
            }
            lrow[r] = lrow[r] * al + sum;
            mrow[r] = mx;
            arow[r] = al;
        }
        __syncthreads();

        // O = O*alpha + P @ V
        float av[4];
        #pragma unroll
        for (int ii = 0; ii < 4; ii++) av[ii] = arow[tr * 4 + ii];
        #pragma unroll
        for (int ii = 0; ii < 4; ii++)
            #pragma unroll
            for (int jj = 0; jj < 4; jj++) o[ii][jj] *= av[ii];

        #pragma unroll 8
        for (int m = 0; m < 64; m++) {
            float4 pf = *(const float4*)&sSt[m * FP + tr * 4];
            float4 vf = *(const float4*)&sV [m * FP + tc * 4];
            float pa[4] = {pf.x, pf.y, pf.z, pf.w};
            float va[4] = {vf.x, vf.y, vf.z, vf.w};
            #pragma unroll
            for (int ii = 0; ii < 4; ii++)
                #pragma unroll
                for (int jj = 0; jj < 4; jj++)
                    o[ii][jj] = fmaf(pa[ii], va[jj], o[ii][jj]);
        }
        __syncthreads();
    }

    // finalize: ctx = O / l
    #pragma unroll
    for (int ii = 0; ii < 4; ii++) {
        const float inv = 1.0f / lrow[tr * 4 + ii];
        const size_t rb = base + (size_t)(r0 + tr * 4 + ii) * Emb + tc * 4;
        float4 ov = make_float4(o[ii][0] * inv, o[ii][1] * inv,
                                o[ii][2] * inv, o[ii][3] * inv);
        *(float4*)&Oo[rb] = ov;
    }
}

// ---------------------------------------------------------------------------
// Launch
// ---------------------------------------------------------------------------
extern "C" void kernel_launch(void* const* d_in, const int* in_sizes, int n_in,
                              void* d_out, int out_size)
{
    const float* x     = (const float*)d_in[0];
    const float* ln1_w = (const float*)d_in[1];
    const float* ln1_b = (const float*)d_in[2];
    const float* wq    = (const float*)d_in[3];
    const float* bq    = (const float*)d_in[4];
    const float* wk    = (const float*)d_in[5];
    const float* bk    = (const float*)d_in[6];
    const float* wv    = (const float*)d_in[7];
    const float* bv    = (const float*)d_in[8];
    const float* wo    = (const float*)d_in[9];
    const float* bo    = (const float*)d_in[10];
    const float* ln2_w = (const float*)d_in[11];
    const float* ln2_b = (const float*)d_in[12];
    const float* wu    = (const float*)d_in[13];
    const float* bu    = (const float*)d_in[14];
    const float* wd    = (const float*)d_in[15];
    const float* bd    = (const float*)d_in[16];
    float* out = (float*)d_out;

    float *xn, *q, *k, *v, *ctx, *hidden, *hn, *up;
    cudaGetSymbolAddress((void**)&xn,     g_xn);
    cudaGetSymbolAddress((void**)&q,      g_q);
    cudaGetSymbolAddress((void**)&k,      g_k);
    cudaGetSymbolAddress((void**)&v,      g_v);
    cudaGetSymbolAddress((void**)&ctx,    g_ctx);
    cudaGetSymbolAddress((void**)&hidden, g_hidden);
    cudaGetSymbolAddress((void**)&hn,     g_hn);
    cudaGetSymbolAddress((void**)&up,     g_up);

    const dim3 gE(Emb / 128, ROWS / 128);   // (8, 32)
    const dim3 gF(FFd / 128, ROWS / 128);   // (32, 32)

    // 1) LN1
    layernorm_kernel<<<ROWS, 256>>>(x, ln1_w, ln1_b, xn);
    // 2) Q, K, V projections
    sgemm_kernel<0><<<gE, 256>>>(xn, wq, bq, nullptr, q, ROWS, Emb, Emb);
    sgemm_kernel<0><<<gE, 256>>>(xn, wk, bk, nullptr, k, ROWS, Emb, Emb);
    sgemm_kernel<0><<<gE, 256>>>(xn, wv, bv, nullptr, v, ROWS, Emb, Emb);
    // 3) Flash attention
    const int shmem = (4 * 64 * FP + 3 * 64) * (int)sizeof(float);  // 70400 B
    cudaFuncSetAttribute(flash_attn_kernel,
                         cudaFuncAttributeMaxDynamicSharedMemorySize, shmem);
    flash_attn_kernel<<<dim3(Lseq / 64, Bb * NH), 256, shmem>>>(q, k, v, ctx);
    // 4) O projection + residual
    sgemm_kernel<1><<<gE, 256>>>(ctx, wo, bo, x, hidden, ROWS, Emb, Emb);
    // 5) LN2
    layernorm_kernel<<<ROWS, 256>>>(hidden, ln2_w, ln2_b, hn);
    // 6) FFN up + GELU
    sgemm_kernel<2><<<gF, 256>>>(hn, wu, bu, nullptr, up, ROWS, FFd, Emb);
    // 7) FFN down + bias + residual -> out
    sgemm_kernel<1><<<gE, 256>>>(up, wd, bd, hidden, out, ROWS, Emb, FFd);
}

// round 5
// speedup vs baseline: 1.8261x; 1.8261x over previous
#include <cuda_runtime.h>
#include <math.h>
#include <stdint.h>

// ---------------------------------------------------------------------------
// Problem constants
// ---------------------------------------------------------------------------
#define Bb   2
#define Lseq 2048
#define Emb  1024
#define NH   16
#define DHd  64
#define FFd  4096
#define ROWS (Bb * Lseq)   // 4096
#define ATTN_SCALE 8.0f    // sqrt(DH) — reference MULTIPLIES by sqrt(dh)

// ---------------------------------------------------------------------------
// Scratch (no allocations allowed: __device__ globals)
// ---------------------------------------------------------------------------
__device__ float g_xn    [ROWS * Emb];
__device__ float g_q     [ROWS * Emb];
__device__ float g_k     [ROWS * Emb];
__device__ float g_v     [ROWS * Emb];
__device__ float g_ctx   [ROWS * Emb];
__device__ float g_hidden[ROWS * Emb];
__device__ float g_hn    [ROWS * Emb];
__device__ float g_up    [ROWS * FFd];

// ---------------------------------------------------------------------------
// LayerNorm: one block per row of 1024, 256 threads, float4
// ---------------------------------------------------------------------------
__global__ void __launch_bounds__(256)
layernorm_kernel(const float* __restrict__ x, const float* __restrict__ w,
                 const float* __restrict__ bsh, float* __restrict__ y)
{
    __shared__ float s1[256];
    __shared__ float s2[256];
    const int tid = threadIdx.x;
    const size_t row = blockIdx.x;
    const float4* xr = (const float4*)(x + row * Emb);
    float4 v = xr[tid];

    float a = v.x + v.y + v.z + v.w;
    float b = v.x * v.x + v.y * v.y + v.z * v.z + v.w * v.w;
    s1[tid] = a; s2[tid] = b;
    __syncthreads();
    #pragma unroll
    for (int st = 128; st > 0; st >>= 1) {
        if (tid < st) { s1[tid] += s1[tid + st]; s2[tid] += s2[tid + st]; }
        __syncthreads();
    }
    const float mu   = s1[0] * (1.0f / Emb);
    const float var  = s2[0] * (1.0f / Emb) - mu * mu;
    const float rstd = rsqrtf(var + 1e-5f);

    float4 wv = ((const float4*)w)[tid];
    float4 bv = ((const float4*)bsh)[tid];
    float4 o;
    o.x = (v.x - mu) * rstd * wv.x + bv.x;
    o.y = (v.y - mu) * rstd * wv.y + bv.y;
    o.z = (v.z - mu) * rstd * wv.z + bv.z;
    o.w = (v.w - mu) * rstd * wv.w + bv.w;
    ((float4*)(y + row * Emb))[tid] = o;
}

// ---------------------------------------------------------------------------
// TF32 tensor-core GEMM: C[M,N] = A[M,K] @ B[K,N] + bias (+res) (+GELU)
// 128x128x32 CTA tile, 256 threads = 8 warps (2 x 4), warp tile 64x32,
// mma.sync.aligned.m16n8k8.row.col.f32.tf32.tf32.f32 (4x4 frags per warp).
// fp32 -> tf32 conversion (round-to-nearest) done once at smem staging.
// Smem layouts picked for zero bank conflicts:
//   As[m][k]  pitch 36  (bank = 4g+tg : all 32 distinct)
//   Bs[k][n]  pitch 136 (bank = 8tg+g : all 32 distinct)
// Double-buffered smem + register prefetch: one __syncthreads per K-tile.
// EPI: 0 = bias, 1 = bias + residual, 2 = bias + exact GELU
// ---------------------------------------------------------------------------
#define BM 128
#define BN 128
#define BK 32
#define PKA 36    // As row pitch (floats)
#define PNB 136   // Bs row pitch (floats)
#define GEMM_SMEM ((2 * BM * PKA + 2 * BK * PNB) * 4)  // 71680 bytes

__device__ __forceinline__ uint32_t f2tf32(float f) {
    uint32_t u;
    asm("cvt.rna.tf32.f32 %0, %1;" : "=r"(u) : "f"(f));
    return u;
}

__device__ __forceinline__ float gelu_exact(float v) {
    return 0.5f * v * (1.0f + erff(v * 0.70710678118654752440f));
}

__device__ __forceinline__ void mma_tf32(float c[4], const uint32_t a[4],
                                         const uint32_t b[2]) {
    asm volatile(
        "mma.sync.aligned.m16n8k8.row.col.f32.tf32.tf32.f32 "
        "{%0,%1,%2,%3}, {%4,%5,%6,%7}, {%8,%9}, {%0,%1,%2,%3};\n"
        : "+f"(c[0]), "+f"(c[1]), "+f"(c[2]), "+f"(c[3])
        : "r"(a[0]), "r"(a[1]), "r"(a[2]), "r"(a[3]), "r"(b[0]), "r"(b[1]));
}

template <int EPI>
__global__ void __launch_bounds__(256)
mma_gemm_kernel(const float* __restrict__ A, const float* __restrict__ B,
                const float* __restrict__ bias, const float* __restrict__ res,
                float* __restrict__ C, int M, int N, int K)
{
    extern __shared__ float smn[];
    float* As = smn;                       // [2][BM][PKA]
    float* Bs = smn + 2 * BM * PKA;        // [2][BK][PNB]

    const int tid  = threadIdx.x;
    const int lane = tid & 31;
    const int warp = tid >> 5;
    const int wm   = (warp >> 2) * 64;     // 0 or 64
    const int wn   = (warp & 3) * 32;      // 0,32,64,96
    const int g    = lane >> 2;            // 0..7
    const int tg   = lane & 3;             // 0..3

    const int bm = blockIdx.y * BM;
    const int bn = blockIdx.x * BN;

    // staging maps
    const int ar = tid >> 3;               // 0..31 (A row, step 32)
    const int ac = (tid & 7) * 4;          // 0..28 (A col)
    const int br = warp;                   // 0..7  (B row, step 8)
    const int bc = lane * 4;               // 0..124 (B col)

    const float* Abase = A + (size_t)(bm + ar) * K + ac;
    const float* Bbase = B + (size_t)br * N + bn + bc;

    float4 ra[4], rb[4];
    #pragma unroll
    for (int i = 0; i < 4; i++)
        ra[i] = *(const float4*)(Abase + (size_t)(32 * i) * K);
    #pragma unroll
    for (int i = 0; i < 4; i++)
        rb[i] = *(const float4*)(Bbase + (size_t)(8 * i) * N);

    // stage tile 0 into buffer 0 (with tf32 rounding)
    #pragma unroll
    for (int i = 0; i < 4; i++) {
        uint32_t* p = (uint32_t*)&As[(ar + 32 * i) * PKA + ac];
        uint4 u = make_uint4(f2tf32(ra[i].x), f2tf32(ra[i].y),
                             f2tf32(ra[i].z), f2tf32(ra[i].w));
        *(uint4*)p = u;
    }
    #pragma unroll
    for (int i = 0; i < 4; i++) {
        uint32_t* p = (uint32_t*)&Bs[(br + 8 * i) * PNB + bc];
        uint4 u = make_uint4(f2tf32(rb[i].x), f2tf32(rb[i].y),
                             f2tf32(rb[i].z), f2tf32(rb[i].w));
        *(uint4*)p = u;
    }
    __syncthreads();

    float acc[4][4][4];
    #pragma unroll
    for (int mi = 0; mi < 4; mi++)
        #pragma unroll
        for (int ni = 0; ni < 4; ni++)
            #pragma unroll
            for (int c = 0; c < 4; c++) acc[mi][ni][c] = 0.0f;

    const int nk = K / BK;
    for (int t = 0; t < nk; t++) {
        const int buf = t & 1;
        // prefetch next tile into registers
        if (t + 1 < nk) {
            const int k0 = (t + 1) * BK;
            #pragma unroll
            for (int i = 0; i < 4; i++)
                ra[i] = *(const float4*)(Abase + (size_t)(32 * i) * K + k0);
            #pragma unroll
            for (int i = 0; i < 4; i++)
                rb[i] = *(const float4*)(Bbase + (size_t)(k0 + 8 * i) * N);
        }

        const float* Asb = As + buf * BM * PKA;
        const float* Bsb = Bs + buf * BK * PNB;

        #pragma unroll
        for (int kk = 0; kk < BK; kk += 8) {
            uint32_t af[4][4], bf[4][2];
            #pragma unroll
            for (int mi = 0; mi < 4; mi++) {
                const int m0 = wm + mi * 16;
                af[mi][0] = __float_as_uint(Asb[(m0 + g) * PKA + kk + tg]);
                af[mi][1] = __float_as_uint(Asb[(m0 + g + 8) * PKA + kk + tg]);
                af[mi][2] = __float_as_uint(Asb[(m0 + g) * PKA + kk + tg + 4]);
                af[mi][3] = __float_as_uint(Asb[(m0 + g + 8) * PKA + kk + tg + 4]);
            }
            #pragma unroll
            for (int ni = 0; ni < 4; ni++) {
                const int n0 = wn + ni * 8;
                bf[ni][0] = __float_as_uint(Bsb[(kk + tg) * PNB + n0 + g]);
                bf[ni][1] = __float_as_uint(Bsb[(kk + tg + 4) * PNB + n0 + g]);
            }
            #pragma unroll
            for (int mi = 0; mi < 4; mi++)
                #pragma unroll
                for (int ni = 0; ni < 4; ni++)
                    mma_tf32(acc[mi][ni], af[mi], bf[ni]);
        }

        if (t + 1 < nk) {
            const int nbuf = (t + 1) & 1;
            float* Asn = As + nbuf * BM * PKA;
            float* Bsn = Bs + nbuf * BK * PNB;
            #pragma unroll
            for (int i = 0; i < 4; i++) {
                uint32_t* p = (uint32_t*)&Asn[(ar + 32 * i) * PKA + ac];
                uint4 u = make_uint4(f2tf32(ra[i].x), f2tf32(ra[i].y),
                                     f2tf32(ra[i].z), f2tf32(ra[i].w));
                *(uint4*)p = u;
            }
            #pragma unroll
            for (int i = 0; i < 4; i++) {
                uint32_t* p = (uint32_t*)&Bsn[(br + 8 * i) * PNB + bc];
                uint4 u = make_uint4(f2tf32(rb[i].x), f2tf32(rb[i].y),
                                     f2tf32(rb[i].z), f2tf32(rb[i].w));
                *(uint4*)p = u;
            }
            __syncthreads();
        }
    }

    // epilogue: c0/c1 at (row g, cols 2*tg, 2*tg+1); c2/c3 at row g+8
    #pragma unroll
    for (int mi = 0; mi < 4; mi++) {
        #pragma unroll
        for (int ni = 0; ni < 4; ni++) {
            const int col = bn + wn + ni * 8 + tg * 2;
            const float bx = bias[col], by = bias[col + 1];
            #pragma unroll
            for (int half = 0; half < 2; half++) {
                const size_t row = (size_t)(bm + wm + mi * 16 + g + half * 8);
                float2 cv;
                cv.x = acc[mi][ni][half * 2 + 0] + bx;
                cv.y = acc[mi][ni][half * 2 + 1] + by;
                if (EPI == 1) {
                    float2 rv = *(const float2*)&res[row * N + col];
                    cv.x += rv.x; cv.y += rv.y;
                }
                if (EPI == 2) {
                    cv.x = gelu_exact(cv.x); cv.y = gelu_exact(cv.y);
                }
                *(float2*)&C[row * N + col] = cv;
            }
        }
    }
}

// ---------------------------------------------------------------------------
// Flash attention (non-causal, full L). One CTA = 64 query rows of one (b,h).
// Unchanged from the passing R3 kernel.
// ---------------------------------------------------------------------------
#define FP 68  // smem pitch (floats)

__global__ void __launch_bounds__(256)
flash_attn_kernel(const float* __restrict__ Q, const float* __restrict__ K,
                  const float* __restrict__ V, float* __restrict__ Oo)
{
    extern __shared__ float sm[];
    float* sQt  = sm;                 // [64][FP]  sQt[d][i]
    float* sKt  = sm + 64 * FP;       // [64][FP]  sKt[d][j]
    float* sV   = sm + 2 * 64 * FP;   // [64][FP]  sV[m][d]
    float* sSt  = sm + 3 * 64 * FP;   // [64][FP]  sSt[m][i]
    float* mrow = sm + 4 * 64 * FP;   // [64]
    float* lrow = mrow + 64;          // [64]
    float* arow = lrow + 64;          // [64]

    const int tid = threadIdx.x;
    const int tr = tid >> 4;
    const int tc = tid & 15;
    const int bh = blockIdx.y;
    const int b = bh >> 4, h = bh & 15;
    const int r0 = blockIdx.x << 6;
    const size_t base = (size_t)b * Lseq * Emb + (size_t)h * DHd;

    for (int idx = tid; idx < 64 * 64; idx += 256) {
        const int i = idx >> 6, d = idx & 63;
        sQt[d * FP + i] = Q[base + (size_t)(r0 + i) * Emb + d];
    }
    if (tid < 64) { mrow[tid] = -1e30f; lrow[tid] = 0.0f; }
    __syncthreads();

    float o[4][4];
    #pragma unroll
    for (int i = 0; i < 4; i++)
        #pragma unroll
        for (int j = 0; j < 4; j++) o[i][j] = 0.0f;

    for (int kb = 0; kb < Lseq / 64; kb++) {
        const int c0 = kb << 6;
        for (int idx = tid; idx < 64 * 64; idx += 256) {
            const int j = idx >> 6, d = idx & 63;
            sKt[d * FP + j] = K[base + (size_t)(c0 + j) * Emb + d];
            sV [j * FP + d] = V[base + (size_t)(c0 + j) * Emb + d];
        }
        __syncthreads();

        float s[4][4];
        #pragma unroll
        for (int i = 0; i < 4; i++)
            #pragma unroll
            for (int j = 0; j < 4; j++) s[i][j] = 0.0f;

        #pragma unroll 8
        for (int d = 0; d < 64; d++) {
            float4 qf = *(const float4*)&sQt[d * FP + tr * 4];
            float4 kf = *(const float4*)&sKt[d * FP + tc * 4];
            float qa[4] = {qf.x, qf.y, qf.z, qf.w};
            float ka[4] = {kf.x, kf.y, kf.z, kf.w};
            #pragma unroll
            for (int i = 0; i < 4; i++)
                #pragma unroll
                for (int j = 0; j < 4; j++)
                    s[i][j] = fmaf(qa[i], ka[j], s[i][j]);
        }
        #pragma unroll
        for (int jj = 0; jj < 4; jj++) {
            float4 wv = make_float4(s[0][jj] * ATTN_SCALE, s[1][jj] * ATTN_SCALE,
                                    s[2][jj] * ATTN_SCALE, s[3][jj] * ATTN_SCALE);
            *(float4*)&sSt[(tc * 4 + jj) * FP + tr * 4] = wv;
        }
        __syncthreads();

        if (tid < 64) {
            const int r = tid;
            float mx = mrow[r];
            #pragma unroll 8
            for (int m = 0; m < 64; m++) mx = fmaxf(mx, sSt[m * FP + r]);
            const float al = __expf(mrow[r] - mx);
            float sum = 0.0f;
            #pragma unroll 8
            for (int m = 0; m < 64; m++) {
                float p = __expf(sSt[m * FP + r] - mx);
                sSt[m * FP + r] = p;
                sum += p;
            }
            lrow[r] = lrow[r] * al + sum;
            mrow[r] = mx;
            arow[r] = al;
        }
        __syncthreads();

        float av[4];
        #pragma unroll
        for (int ii = 0; ii < 4; ii++) av[ii] = arow[tr * 4 + ii];
        #pragma unroll
        for (int ii = 0; ii < 4; ii++)
            #pragma unroll
            for (int jj = 0; jj < 4; jj++) o[ii][jj] *= av[ii];

        #pragma unroll 8
        for (int m = 0; m < 64; m++) {
            float4 pf = *(const float4*)&sSt[m * FP + tr * 4];
            float4 vf = *(const float4*)&sV [m * FP + tc * 4];
            float pa[4] = {pf.x, pf.y, pf.z, pf.w};
            float va[4] = {vf.x, vf.y, vf.z, vf.w};
            #pragma unroll
            for (int ii = 0; ii < 4; ii++)
                #pragma unroll
                for (int jj = 0; jj < 4; jj++)
                    o[ii][jj] = fmaf(pa[ii], va[jj], o[ii][jj]);
        }
        __syncthreads();
    }

    #pragma unroll
    for (int ii = 0; ii < 4; ii++) {
        const float inv = 1.0f / lrow[tr * 4 + ii];
        const size_t rb = base + (size_t)(r0 + tr * 4 + ii) * Emb + tc * 4;
        float4 ov = make_float4(o[ii][0] * inv, o[ii][1] * inv,
                                o[ii][2] * inv, o[ii][3] * inv);
        *(float4*)&Oo[rb] = ov;
    }
}

// ---------------------------------------------------------------------------
// Launch
// ---------------------------------------------------------------------------
extern "C" void kernel_launch(void* const* d_in, const int* in_sizes, int n_in,
                              void* d_out, int out_size)
{
    const float* x     = (const float*)d_in[0];
    const float* ln1_w = (const float*)d_in[1];
    const float* ln1_b = (const float*)d_in[2];
    const float* wq    = (const float*)d_in[3];
    const float* bq    = (const float*)d_in[4];
    const float* wk    = (const float*)d_in[5];
    const float* bk    = (const float*)d_in[6];
    const float* wv    = (const float*)d_in[7];
    const float* bv    = (const float*)d_in[8];
    const float* wo    = (const float*)d_in[9];
    const float* bo    = (const float*)d_in[10];
    const float* ln2_w = (const float*)d_in[11];
    const float* ln2_b = (const float*)d_in[12];
    const float* wu    = (const float*)d_in[13];
    const float* bu    = (const float*)d_in[14];
    const float* wd    = (const float*)d_in[15];
    const float* bd    = (const float*)d_in[16];
    float* out = (float*)d_out;

    float *xn, *q, *k, *v, *ctx, *hidden, *hn, *up;
    cudaGetSymbolAddress((void**)&xn,     g_xn);
    cudaGetSymbolAddress((void**)&q,      g_q);
    cudaGetSymbolAddress((void**)&k,      g_k);
    cudaGetSymbolAddress((void**)&v,      g_v);
    cudaGetSymbolAddress((void**)&ctx,    g_ctx);
    cudaGetSymbolAddress((void**)&hidden, g_hidden);
    cudaGetSymbolAddress((void**)&hn,     g_hn);
    cudaGetSymbolAddress((void**)&up,     g_up);

    cudaFuncSetAttribute(mma_gemm_kernel<0>,
                         cudaFuncAttributeMaxDynamicSharedMemorySize, GEMM_SMEM);
    cudaFuncSetAttribute(mma_gemm_kernel<1>,
                         cudaFuncAttributeMaxDynamicSharedMemorySize, GEMM_SMEM);
    cudaFuncSetAttribute(mma_gemm_kernel<2>,
                         cudaFuncAttributeMaxDynamicSharedMemorySize, GEMM_SMEM);

    const dim3 gE(Emb / 128, ROWS / 128);   // (8, 32)
    const dim3 gF(FFd / 128, ROWS / 128);   // (32, 32)

    // 1) LN1
    layernorm_kernel<<<ROWS, 256>>>(x, ln1_w, ln1_b, xn);
    // 2) Q, K, V projections (TF32 tensor cores)
    mma_gemm_kernel<0><<<gE, 256, GEMM_SMEM>>>(xn, wq, bq, nullptr, q, ROWS, Emb, Emb);
    mma_gemm_kernel<0><<<gE, 256, GEMM_SMEM>>>(xn, wk, bk, nullptr, k, ROWS, Emb, Emb);
    mma_gemm_kernel<0><<<gE, 256, GEMM_SMEM>>>(xn, wv, bv, nullptr, v, ROWS, Emb, Emb);
    // 3) Flash attention
    const int shmem = (4 * 64 * FP + 3 * 64) * (int)sizeof(float);  // 70400 B
    cudaFuncSetAttribute(flash_attn_kernel,
                         cudaFuncAttributeMaxDynamicSharedMemorySize, shmem);
    flash_attn_kernel<<<dim3(Lseq / 64, Bb * NH), 256, shmem>>>(q, k, v, ctx);
    // 4) O projection + residual
    mma_gemm_kernel<1><<<gE, 256, GEMM_SMEM>>>(ctx, wo, bo, x, hidden, ROWS, Emb, Emb);
    // 5) LN2
    layernorm_kernel<<<ROWS, 256>>>(hidden, ln2_w, ln2_b, hn);
    // 6) FFN up + GELU
    mma_gemm_kernel<2><<<gF, 256, GEMM_SMEM>>>(hn, wu, bu, nullptr, up, ROWS, FFd, Emb);
    // 7) FFN down + bias + residual -> out
    mma_gemm_kernel<1><<<gE, 256, GEMM_SMEM>>>(up, wd, bd, hidden, out, ROWS, Emb, FFd);
}

// round 6
// speedup vs baseline: 2.1005x; 1.1502x over previous
#include <cuda_runtime.h>
#include <cuda_bf16.h>
#include <math.h>
#include <stdint.h>

// ---------------------------------------------------------------------------
// Problem constants
// ---------------------------------------------------------------------------
#define Bb   2
#define Lseq 2048
#define Emb  1024
#define NH   16
#define DHd  64
#define FFd  4096
#define ROWS (Bb * Lseq)   // 4096
// reference MULTIPLIES scores by sqrt(dh) = 8 (exact power of two)

// ---------------------------------------------------------------------------
// Scratch (no allocations allowed: __device__ globals)
// ---------------------------------------------------------------------------
__device__ float g_xn    [ROWS * Emb];
__device__ float g_q     [ROWS * Emb];
__device__ float g_k     [ROWS * Emb];
__device__ float g_v     [ROWS * Emb];
__device__ float g_ctx   [ROWS * Emb];
__device__ float g_hidden[ROWS * Emb];
__device__ float g_hn    [ROWS * Emb];
__device__ float g_up    [ROWS * FFd];

// ---------------------------------------------------------------------------
// Small helpers: bf16 split (x = xh + xl), ldmatrix, mma
// ---------------------------------------------------------------------------
__device__ __forceinline__ uint32_t cvta_s(const void* p) {
    return (uint32_t)__cvta_generic_to_shared(p);
}

__device__ __forceinline__ void splitpack(float a, float b, uint32_t& h, uint32_t& l) {
    __nv_bfloat16 ha = __float2bfloat16(a), hb = __float2bfloat16(b);
    __nv_bfloat16 la = __float2bfloat16(a - __bfloat162float(ha));
    __nv_bfloat16 lb = __float2bfloat16(b - __bfloat162float(hb));
    h = ((uint32_t)__bfloat16_as_ushort(hb) << 16) | (uint32_t)__bfloat16_as_ushort(ha);
    l = ((uint32_t)__bfloat16_as_ushort(lb) << 16) | (uint32_t)__bfloat16_as_ushort(la);
}

__device__ __forceinline__ void split_store4(float4 v, __nv_bfloat16* h, __nv_bfloat16* l) {
    uint32_t h01, l01, h23, l23;
    splitpack(v.x, v.y, h01, l01);
    splitpack(v.z, v.w, h23, l23);
    ((uint32_t*)h)[0] = h01; ((uint32_t*)h)[1] = h23;
    ((uint32_t*)l)[0] = l01; ((uint32_t*)l)[1] = l23;
}

__device__ __forceinline__ void ldsm_x4(uint32_t r[4], uint32_t a) {
    asm volatile("ldmatrix.sync.aligned.m8n8.x4.shared.b16 {%0,%1,%2,%3}, [%4];"
                 : "=r"(r[0]), "=r"(r[1]), "=r"(r[2]), "=r"(r[3]) : "r"(a));
}
__device__ __forceinline__ void ldsm_x2(uint32_t r[2], uint32_t a) {
    asm volatile("ldmatrix.sync.aligned.m8n8.x2.shared.b16 {%0,%1}, [%2];"
                 : "=r"(r[0]), "=r"(r[1]) : "r"(a));
}
__device__ __forceinline__ void ldsm_x2t(uint32_t r[2], uint32_t a) {
    asm volatile("ldmatrix.sync.aligned.m8n8.x2.trans.shared.b16 {%0,%1}, [%2];"
                 : "=r"(r[0]), "=r"(r[1]) : "r"(a));
}
__device__ __forceinline__ void mma_bf16(float c[4], const uint32_t a[4], const uint32_t b[2]) {
    asm volatile("mma.sync.aligned.m16n8k16.row.col.f32.bf16.bf16.f32 "
                 "{%0,%1,%2,%3}, {%4,%5,%6,%7}, {%8,%9}, {%0,%1,%2,%3};"
                 : "+f"(c[0]), "+f"(c[1]), "+f"(c[2]), "+f"(c[3])
                 : "r"(a[0]), "r"(a[1]), "r"(a[2]), "r"(a[3]), "r"(b[0]), "r"(b[1]));
}

__device__ __forceinline__ float gelu_exact(float v) {
    return 0.5f * v * (1.0f + erff(v * 0.70710678118654752440f));
}

// ---------------------------------------------------------------------------
// LayerNorm: one block per row of 1024, 256 threads, float4
// ---------------------------------------------------------------------------
__global__ void __launch_bounds__(256)
layernorm_kernel(const float* __restrict__ x, const float* __restrict__ w,
                 const float* __restrict__ bsh, float* __restrict__ y)
{
    __shared__ float s1[256];
    __shared__ float s2[256];
    const int tid = threadIdx.x;
    const size_t row = blockIdx.x;
    const float4* xr = (const float4*)(x + row * Emb);
    float4 v = xr[tid];

    float a = v.x + v.y + v.z + v.w;
    float b = v.x * v.x + v.y * v.y + v.z * v.z + v.w * v.w;
    s1[tid] = a; s2[tid] = b;
    __syncthreads();
    #pragma unroll
    for (int st = 128; st > 0; st >>= 1) {
        if (tid < st) { s1[tid] += s1[tid + st]; s2[tid] += s2[tid + st]; }
        __syncthreads();
    }
    const float mu   = s1[0] * (1.0f / Emb);
    const float var  = s2[0] * (1.0f / Emb) - mu * mu;
    const float rstd = rsqrtf(var + 1e-5f);

    float4 wv = ((const float4*)w)[tid];
    float4 bv = ((const float4*)bsh)[tid];
    float4 o;
    o.x = (v.x - mu) * rstd * wv.x + bv.x;
    o.y = (v.y - mu) * rstd * wv.y + bv.y;
    o.z = (v.z - mu) * rstd * wv.z + bv.z;
    o.w = (v.w - mu) * rstd * wv.w + bv.w;
    ((float4*)(y + row * Emb))[tid] = o;
}

// ---------------------------------------------------------------------------
// bf16-split tensor-core GEMM: C = A @ B + bias (+res) (+GELU), near-fp32 acc.
// 128x128x32 CTA tile, 8 warps (2x4), warp tile 64x32.
// A,B staged to smem as (high, low) bf16 pairs; fragments via ldmatrix;
// per fragment-pair 3 MMAs: Ah*Bh + Al*Bh + Ah*Bl  (drops O(2^-18) terms).
// Double-buffered smem + register prefetch.
// EPI: 0 = bias, 1 = bias + residual, 2 = bias + exact GELU
// ---------------------------------------------------------------------------
#define BM 128
#define BN 128
#define BK 32
#define PA 40    // bf16 pitch of A tiles  (80B rows: ldmatrix conflict-free)
#define PB 136   // bf16 pitch of B tiles  (272B rows: conflict-free)
#define A_ELE (BM * PA)   // 5120
#define B_ELE (BK * PB)   // 4352
#define GEMM_SMEM ((4 * A_ELE + 4 * B_ELE) * 2)  // 75776 bytes

template <int EPI>
__global__ void __launch_bounds__(256)
mma_gemm_kernel(const float* __restrict__ A, const float* __restrict__ B,
                const float* __restrict__ bias, const float* __restrict__ res,
                float* __restrict__ C, int M, int N, int K)
{
    extern __shared__ __nv_bfloat16 smb[];
    __nv_bfloat16* Ah = smb;                    // [2][BM][PA]
    __nv_bfloat16* Al = smb + 2 * A_ELE;
    __nv_bfloat16* Bh = smb + 4 * A_ELE;        // [2][BK][PB]
    __nv_bfloat16* Bl = smb + 4 * A_ELE + 2 * B_ELE;

    const int tid  = threadIdx.x;
    const int lane = tid & 31;
    const int warp = tid >> 5;
    const int wm   = (warp >> 2) * 64;
    const int wn   = (warp & 3) * 32;
    const int g    = lane >> 2;
    const int tg   = lane & 3;

    const int bm = blockIdx.y * BM;
    const int bn = blockIdx.x * BN;

    // staging maps
    const int ar = tid >> 3;               // 0..31 (A row, step 32)
    const int ac = (tid & 7) * 4;          // 0..28
    const int br = tid >> 5;               // 0..7  (B row, step 8)
    const int bc = (tid & 31) * 4;         // 0..124

    const float* Abase = A + (size_t)(bm + ar) * K + ac;
    const float* Bbase = B + (size_t)br * N + bn + bc;

    float4 ra[4], rb[4];
    #pragma unroll
    for (int i = 0; i < 4; i++)
        ra[i] = *(const float4*)(Abase + (size_t)(32 * i) * K);
    #pragma unroll
    for (int i = 0; i < 4; i++)
        rb[i] = *(const float4*)(Bbase + (size_t)(8 * i) * N);

    // stage tile 0 into buffer 0
    #pragma unroll
    for (int i = 0; i < 4; i++) {
        const int off = (ar + 32 * i) * PA + ac;
        split_store4(ra[i], Ah + off, Al + off);
    }
    #pragma unroll
    for (int i = 0; i < 4; i++) {
        const int off = (br + 8 * i) * PB + bc;
        split_store4(rb[i], Bh + off, Bl + off);
    }
    __syncthreads();

    float acc[4][4][4];
    #pragma unroll
    for (int mi = 0; mi < 4; mi++)
        #pragma unroll
        for (int ni = 0; ni < 4; ni++)
            #pragma unroll
            for (int c = 0; c < 4; c++) acc[mi][ni][c] = 0.0f;

    // ldmatrix lane geometry
    const int a_r  = (lane & 7) + ((lane >> 3) & 1) * 8;   // row within 16
    const int a_kh = (lane >> 4) * 8;                      // k-half offset
    const int b_r  = lane & 15;                            // row within 16

    const int nk = K / BK;
    for (int t = 0; t < nk; t++) {
        const int buf = t & 1;
        if (t + 1 < nk) {
            const int k0 = (t + 1) * BK;
            #pragma unroll
            for (int i = 0; i < 4; i++)
                ra[i] = *(const float4*)(Abase + (size_t)(32 * i) * K + k0);
            #pragma unroll
            for (int i = 0; i < 4; i++)
                rb[i] = *(const float4*)(Bbase + (size_t)(k0 + 8 * i) * N);
        }

        const __nv_bfloat16* Ahb = Ah + buf * A_ELE;
        const __nv_bfloat16* Alb = Al + buf * A_ELE;
        const __nv_bfloat16* Bhb = Bh + buf * B_ELE;
        const __nv_bfloat16* Blb = Bl + buf * B_ELE;

        #pragma unroll
        for (int kk = 0; kk < BK; kk += 16) {
            uint32_t ah[4][4], al[4][4];
            #pragma unroll
            for (int mi = 0; mi < 4; mi++) {
                const int row = wm + mi * 16 + a_r;
                const int kc  = kk + a_kh;
                ldsm_x4(ah[mi], cvta_s(Ahb + row * PA + kc));
                ldsm_x4(al[mi], cvta_s(Alb + row * PA + kc));
            }
            #pragma unroll
            for (int ni = 0; ni < 4; ni++) {
                const int n0 = wn + ni * 8;
                uint32_t bh2[2], bl2[2];
                const int boff = (kk + b_r) * PB + n0;
                ldsm_x2t(bh2, cvta_s(Bhb + boff));
                ldsm_x2t(bl2, cvta_s(Blb + boff));
                #pragma unroll
                for (int mi = 0; mi < 4; mi++) {
                    mma_bf16(acc[mi][ni], ah[mi], bh2);
                    mma_bf16(acc[mi][ni], al[mi], bh2);
                    mma_bf16(acc[mi][ni], ah[mi], bl2);
                }
            }
        }

        if (t + 1 < nk) {
            const int nbuf = (t + 1) & 1;
            __nv_bfloat16* Ahn = Ah + nbuf * A_ELE;
            __nv_bfloat16* Aln = Al + nbuf * A_ELE;
            __nv_bfloat16* Bhn = Bh + nbuf * B_ELE;
            __nv_bfloat16* Bln = Bl + nbuf * B_ELE;
            #pragma unroll
            for (int i = 0; i < 4; i++) {
                const int off = (ar + 32 * i) * PA + ac;
                split_store4(ra[i], Ahn + off, Aln + off);
            }
            #pragma unroll
            for (int i = 0; i < 4; i++) {
                const int off = (br + 8 * i) * PB + bc;
                split_store4(rb[i], Bhn + off, Bln + off);
            }
            __syncthreads();
        }
    }

    // epilogue: c0/c1 at (row g, cols 2tg,2tg+1); c2/c3 at row g+8
    #pragma unroll
    for (int mi = 0; mi < 4; mi++) {
        #pragma unroll
        for (int ni = 0; ni < 4; ni++) {
            const int col = bn + wn + ni * 8 + tg * 2;
            const float bx = bias[col], by = bias[col + 1];
            #pragma unroll
            for (int half = 0; half < 2; half++) {
                const size_t row = (size_t)(bm + wm + mi * 16 + g + half * 8);
                float2 cv;
                cv.x = acc[mi][ni][half * 2 + 0] + bx;
                cv.y = acc[mi][ni][half * 2 + 1] + by;
                if (EPI == 1) {
                    float2 rv = *(const float2*)&res[row * N + col];
                    cv.x += rv.x; cv.y += rv.y;
                }
                if (EPI == 2) {
                    cv.x = gelu_exact(cv.x); cv.y = gelu_exact(cv.y);
                }
                *(float2*)&C[row * N + col] = cv;
            }
        }
    }
}

// ---------------------------------------------------------------------------
// Tensor-core flash attention (bf16 split, FA2-style register softmax).
// CTA = 128 query rows of one (b,h), 8 warps, each warp owns 16 rows.
// K-tiles of 64 keys.  S = (8*Q) K^T via 3-mma bf16 split (scale folded
// into Q exactly — 8 is a power of two).  P built in-register from S frags
// (C-frag == A-frag identity), split to bf16 h/l, PV via 3-mma split.
// Smem: Qh/Ql [128][72] + Kh/Kl/Vh/Vl [64][72] bf16 = 73728 B.
// ---------------------------------------------------------------------------
#define PQ 72
#define ATTN_SMEM ((2 * 128 * PQ + 4 * 64 * PQ) * 2)  // 73728 bytes

__global__ void __launch_bounds__(256)
flash_attn_kernel(const float* __restrict__ Q, const float* __restrict__ K,
                  const float* __restrict__ V, float* __restrict__ Oo)
{
    extern __shared__ __nv_bfloat16 sb[];
    __nv_bfloat16* Qh = sb;
    __nv_bfloat16* Ql = sb + 128 * PQ;
    __nv_bfloat16* Kh = sb + 2 * 128 * PQ;
    __nv_bfloat16* Kl = Kh + 64 * PQ;
    __nv_bfloat16* Vh = Kl + 64 * PQ;
    __nv_bfloat16* Vl = Vh + 64 * PQ;

    const int tid  = threadIdx.x;
    const int lane = tid & 31;
    const int warp = tid >> 5;
    const int g    = lane >> 2;
    const int tg   = lane & 3;

    const int bh = blockIdx.y;
    const int b = bh >> 4, h = bh & 15;
    const int q0 = blockIdx.x << 7;     // 128 q-rows per CTA
    const size_t base = (size_t)b * Lseq * Emb + (size_t)h * DHd;

    // ---- stage Q (scaled by 8, split) ----
    #pragma unroll
    for (int i = 0; i < 8; i++) {
        const int idx = tid + 256 * i;
        const int r = idx >> 4, c = (idx & 15) * 4;
        float4 qv = *(const float4*)&Q[base + (size_t)(q0 + r) * Emb + c];
        qv.x *= 8.0f; qv.y *= 8.0f; qv.z *= 8.0f; qv.w *= 8.0f;
        split_store4(qv, Qh + r * PQ + c, Ql + r * PQ + c);
    }
    __syncthreads();

    // ---- Q fragments, held in registers ----
    const int a_r  = (lane & 7) + ((lane >> 3) & 1) * 8;
    const int a_kh = (lane >> 4) * 8;
    uint32_t qfh[4][4], qfl[4][4];
    {
        const int row = warp * 16 + a_r;
        #pragma unroll
        for (int ks = 0; ks < 4; ks++) {
            const int kc = 16 * ks + a_kh;
            ldsm_x4(qfh[ks], cvta_s(Qh + row * PQ + kc));
            ldsm_x4(qfl[ks], cvta_s(Ql + row * PQ + kc));
        }
    }

    float oacc[8][4];
    #pragma unroll
    for (int nj = 0; nj < 8; nj++)
        #pragma unroll
        for (int c = 0; c < 4; c++) oacc[nj][c] = 0.0f;
    float mA = -1e30f, mB = -1e30f, lA = 0.0f, lB = 0.0f;

    for (int kb = 0; kb < Lseq / 64; kb++) {
        const int c0 = kb << 6;
        // ---- stage K, V tiles (split) ----
        #pragma unroll
        for (int i = 0; i < 4; i++) {
            const int idx = tid + 256 * i;
            const int r = idx >> 4, c = (idx & 15) * 4;
            float4 kv = *(const float4*)&K[base + (size_t)(c0 + r) * Emb + c];
            float4 vv = *(const float4*)&V[base + (size_t)(c0 + r) * Emb + c];
            split_store4(kv, Kh + r * PQ + c, Kl + r * PQ + c);
            split_store4(vv, Vh + r * PQ + c, Vl + r * PQ + c);
        }
        __syncthreads();

        // ---- S = (8Q) K^T : 8 n-frags (keys), 4 k-steps (d) ----
        float sacc[8][4];
        #pragma unroll
        for (int ni = 0; ni < 8; ni++)
            #pragma unroll
            for (int c = 0; c < 4; c++) sacc[ni][c] = 0.0f;

        // QK B-frag: NON-trans ldmatrix; matrix0 = keys n0..n0+7 x d kk..kk+7,
        // matrix1 = same keys, d kk+8..kk+15.
        const int qk_row = lane & 7;
        const int qk_kh  = ((lane >> 3) & 1) * 8;
        #pragma unroll
        for (int ks = 0; ks < 4; ks++) {
            #pragma unroll
            for (int ni = 0; ni < 8; ni++) {
                const int n0 = ni * 8;
                uint32_t kh2[2], kl2[2];
                const int koff = (n0 + qk_row) * PQ + 16 * ks + qk_kh;
                ldsm_x2(kh2, cvta_s(Kh + koff));
                ldsm_x2(kl2, cvta_s(Kl + koff));
                mma_bf16(sacc[ni], qfh[ks], kh2);
                mma_bf16(sacc[ni], qfl[ks], kh2);
                mma_bf16(sacc[ni], qfh[ks], kl2);
            }
        }

        // ---- online softmax (register-resident; rows g and g+8) ----
        float tA = -1e30f, tB = -1e30f;
        #pragma unroll
        for (int ni = 0; ni < 8; ni++) {
            tA = fmaxf(tA, fmaxf(sacc[ni][0], sacc[ni][1]));
            tB = fmaxf(tB, fmaxf(sacc[ni][2], sacc[ni][3]));
        }
        tA = fmaxf(tA, __shfl_xor_sync(0xffffffffu, tA, 1));
        tA = fmaxf(tA, __shfl_xor_sync(0xffffffffu, tA, 2));
        tB = fmaxf(tB, __shfl_xor_sync(0xffffffffu, tB, 1));
        tB = fmaxf(tB, __shfl_xor_sync(0xffffffffu, tB, 2));

        const float mAn = fmaxf(mA, tA), mBn = fmaxf(mB, tB);
        const float aA = __expf(mA - mAn), aB = __expf(mB - mBn);
        mA = mAn; mB = mBn;

        float sA = 0.0f, sB = 0.0f;
        #pragma unroll
        for (int ni = 0; ni < 8; ni++) {
            float p0 = __expf(sacc[ni][0] - mAn);
            float p1 = __expf(sacc[ni][1] - mAn);
            float p2 = __expf(sacc[ni][2] - mBn);
            float p3 = __expf(sacc[ni][3] - mBn);
            sacc[ni][0] = p0; sacc[ni][1] = p1;
            sacc[ni][2] = p2; sacc[ni][3] = p3;
            sA += p0 + p1; sB += p2 + p3;
        }
        sA += __shfl_xor_sync(0xffffffffu, sA, 1);
        sA += __shfl_xor_sync(0xffffffffu, sA, 2);
        sB += __shfl_xor_sync(0xffffffffu, sB, 1);
        sB += __shfl_xor_sync(0xffffffffu, sB, 2);
        lA = lA * aA + sA;
        lB = lB * aB + sB;

        #pragma unroll
        for (int nj = 0; nj < 8; nj++) {
            oacc[nj][0] *= aA; oacc[nj][1] *= aA;
            oacc[nj][2] *= aB; oacc[nj][3] *= aB;
        }

        // ---- O += P V : P a-frags straight from S c-frags (split) ----
        #pragma unroll
        for (int ks = 0; ks < 4; ks++) {
            uint32_t pfh[4], pfl[4];
            splitpack(sacc[2 * ks][0],     sacc[2 * ks][1],     pfh[0], pfl[0]);
            splitpack(sacc[2 * ks][2],     sacc[2 * ks][3],     pfh[1], pfl[1]);
            splitpack(sacc[2 * ks + 1][0], sacc[2 * ks + 1][1], pfh[2], pfl[2]);
            splitpack(sacc[2 * ks + 1][2], sacc[2 * ks + 1][3], pfh[3], pfl[3]);
            #pragma unroll
            for (int nj = 0; nj < 8; nj++) {
                const int n0 = nj * 8;
                uint32_t vh2[2], vl2[2];
                const int voff = (16 * ks + (lane & 15)) * PQ + n0;
                ldsm_x2t(vh2, cvta_s(Vh + voff));
                ldsm_x2t(vl2, cvta_s(Vl + voff));
                mma_bf16(oacc[nj], pfh, vh2);
                mma_bf16(oacc[nj], pfl, vh2);
                mma_bf16(oacc[nj], pfh, vl2);
            }
        }
        __syncthreads();   // before next tile's K/V overwrite
    }

    // ---- finalize: ctx = O / l ----
    const float iA = 1.0f / lA, iB = 1.0f / lB;
    const int rowA = q0 + warp * 16 + g;
    #pragma unroll
    for (int nj = 0; nj < 8; nj++) {
        const int d = nj * 8 + tg * 2;
        float2 oA = make_float2(oacc[nj][0] * iA, oacc[nj][1] * iA);
        float2 oB = make_float2(oacc[nj][2] * iB, oacc[nj][3] * iB);
        *(float2*)&Oo[base + (size_t)rowA * Emb + d]       = oA;
        *(float2*)&Oo[base + (size_t)(rowA + 8) * Emb + d] = oB;
    }
}

// ---------------------------------------------------------------------------
// Launch
// ---------------------------------------------------------------------------
extern "C" void kernel_launch(void* const* d_in, const int* in_sizes, int n_in,
                              void* d_out, int out_size)
{
    const float* x     = (const float*)d_in[0];
    const float* ln1_w = (const float*)d_in[1];
    const float* ln1_b = (const float*)d_in[2];
    const float* wq    = (const float*)d_in[3];
    const float* bq    = (const float*)d_in[4];
    const float* wk    = (const float*)d_in[5];
    const float* bk    = (const float*)d_in[6];
    const float* wv    = (const float*)d_in[7];
    const float* bv    = (const float*)d_in[8];
    const float* wo    = (const float*)d_in[9];
    const float* bo    = (const float*)d_in[10];
    const float* ln2_w = (const float*)d_in[11];
    const float* ln2_b = (const float*)d_in[12];
    const float* wu    = (const float*)d_in[13];
    const float* bu    = (const float*)d_in[14];
    const float* wd    = (const float*)d_in[15];
    const float* bd    = (const float*)d_in[16];
    float* out = (float*)d_out;

    float *xn, *q, *k, *v, *ctx, *hidden, *hn, *up;
    cudaGetSymbolAddress((void**)&xn,     g_xn);
    cudaGetSymbolAddress((void**)&q,      g_q);
    cudaGetSymbolAddress((void**)&k,      g_k);
    cudaGetSymbolAddress((void**)&v,      g_v);
    cudaGetSymbolAddress((void**)&ctx,    g_ctx);
    cudaGetSymbolAddress((void**)&hidden, g_hidden);
    cudaGetSymbolAddress((void**)&hn,     g_hn);
    cudaGetSymbolAddress((void**)&up,     g_up);

    cudaFuncSetAttribute(mma_gemm_kernel<0>,
                         cudaFuncAttributeMaxDynamicSharedMemorySize, GEMM_SMEM);
    cudaFuncSetAttribute(mma_gemm_kernel<1>,
                         cudaFuncAttributeMaxDynamicSharedMemorySize, GEMM_SMEM);
    cudaFuncSetAttribute(mma_gemm_kernel<2>,
                         cudaFuncAttributeMaxDynamicSharedMemorySize, GEMM_SMEM);
    cudaFuncSetAttribute(flash_attn_kernel,
                         cudaFuncAttributeMaxDynamicSharedMemorySize, ATTN_SMEM);

    const dim3 gE(Emb / 128, ROWS / 128);   // (8, 32)
    const dim3 gF(FFd / 128, ROWS / 128);   // (32, 32)

    // 1) LN1
    layernorm_kernel<<<ROWS, 256>>>(x, ln1_w, ln1_b, xn);
    // 2) Q, K, V projections (bf16-split tensor cores)
    mma_gemm_kernel<0><<<gE, 256, GEMM_SMEM>>>(xn, wq, bq, nullptr, q, ROWS, Emb, Emb);
    mma_gemm_kernel<0><<<gE, 256, GEMM_SMEM>>>(xn, wk, bk, nullptr, k, ROWS, Emb, Emb);
    mma_gemm_kernel<0><<<gE, 256, GEMM_SMEM>>>(xn, wv, bv, nullptr, v, ROWS, Emb, Emb);
    // 3) Flash attention (bf16-split tensor cores)
    flash_attn_kernel<<<dim3(Lseq / 128, Bb * NH), 256, ATTN_SMEM>>>(q, k, v, ctx);
    // 4) O projection + residual
    mma_gemm_kernel<1><<<gE, 256, GEMM_SMEM>>>(ctx, wo, bo, x, hidden, ROWS, Emb, Emb);
    // 5) LN2
    layernorm_kernel<<<ROWS, 256>>>(hidden, ln2_w, ln2_b, hn);
    // 6) FFN up + GELU
    mma_gemm_kernel<2><<<gF, 256, GEMM_SMEM>>>(hn, wu, bu, nullptr, up, ROWS, FFd, Emb);
    // 7) FFN down + bias + residual -> out
    mma_gemm_kernel<1><<<gE, 256, GEMM_SMEM>>>(up, wd, bd, hidden, out, ROWS, Emb, FFd);
}

// round 8
// speedup vs baseline: 2.3105x; 1.1000x over previous
#include <cuda_runtime.h>
#include <cuda_bf16.h>
#include <math.h>
#include <stdint.h>

// ---------------------------------------------------------------------------
// Problem constants
// ---------------------------------------------------------------------------
#define Bb   2
#define Lseq 2048
#define Emb  1024
#define NH   16
#define DHd  64
#define FFd  4096
#define ROWS (Bb * Lseq)   // 4096
// reference MULTIPLIES scores by sqrt(dh) = 8 (exact power of two)

// ---------------------------------------------------------------------------
// Scratch (no allocations allowed: __device__ globals)
// ---------------------------------------------------------------------------
__device__ __nv_bfloat16 g_xn_h [ROWS * Emb];
__device__ __nv_bfloat16 g_xn_l [ROWS * Emb];
__device__ __nv_bfloat16 g_hn_h [ROWS * Emb];
__device__ __nv_bfloat16 g_hn_l [ROWS * Emb];
__device__ __nv_bfloat16 g_ctx_h[ROWS * Emb];
__device__ __nv_bfloat16 g_ctx_l[ROWS * Emb];
__device__ __nv_bfloat16 g_up_h [ROWS * FFd];
__device__ __nv_bfloat16 g_up_l [ROWS * FFd];
__device__ float g_q     [ROWS * Emb];
__device__ float g_k     [ROWS * Emb];
__device__ float g_v     [ROWS * Emb];
__device__ float g_hidden[ROWS * Emb];
// split weights, ORIGINAL [K, N] layout, bf16 h/l
__device__ __nv_bfloat16 g_wq_h[Emb * Emb], g_wq_l[Emb * Emb];
__device__ __nv_bfloat16 g_wk_h[Emb * Emb], g_wk_l[Emb * Emb];
__device__ __nv_bfloat16 g_wv_h[Emb * Emb], g_wv_l[Emb * Emb];
__device__ __nv_bfloat16 g_wo_h[Emb * Emb], g_wo_l[Emb * Emb];
__device__ __nv_bfloat16 g_wu_h[Emb * FFd], g_wu_l[Emb * FFd];
__device__ __nv_bfloat16 g_wd_h[FFd * Emb], g_wd_l[FFd * Emb];

// ---------------------------------------------------------------------------
// Helpers
// ---------------------------------------------------------------------------
__device__ __forceinline__ uint32_t cvta_s(const void* p) {
    return (uint32_t)__cvta_generic_to_shared(p);
}

__device__ __forceinline__ void splitpack(float a, float b, uint32_t& h, uint32_t& l) {
    __nv_bfloat16 ha = __float2bfloat16(a), hb = __float2bfloat16(b);
    __nv_bfloat16 la = __float2bfloat16(a - __bfloat162float(ha));
    __nv_bfloat16 lb = __float2bfloat16(b - __bfloat162float(hb));
    h = ((uint32_t)__bfloat16_as_ushort(hb) << 16) | (uint32_t)__bfloat16_as_ushort(ha);
    l = ((uint32_t)__bfloat16_as_ushort(lb) << 16) | (uint32_t)__bfloat16_as_ushort(la);
}

__device__ __forceinline__ void split_store4(float4 v, __nv_bfloat16* h, __nv_bfloat16* l) {
    uint32_t h01, l01, h23, l23;
    splitpack(v.x, v.y, h01, l01);
    splitpack(v.z, v.w, h23, l23);
    ((uint32_t*)h)[0] = h01; ((uint32_t*)h)[1] = h23;
    ((uint32_t*)l)[0] = l01; ((uint32_t*)l)[1] = l23;
}

__device__ __forceinline__ void ldsm_x4(uint32_t r[4], uint32_t a) {
    asm volatile("ldmatrix.sync.aligned.m8n8.x4.shared.b16 {%0,%1,%2,%3}, [%4];"
                 : "=r"(r[0]), "=r"(r[1]), "=r"(r[2]), "=r"(r[3]) : "r"(a));
}
__device__ __forceinline__ void ldsm_x2(uint32_t r[2], uint32_t a) {
    asm volatile("ldmatrix.sync.aligned.m8n8.x2.shared.b16 {%0,%1}, [%2];"
                 : "=r"(r[0]), "=r"(r[1]) : "r"(a));
}
__device__ __forceinline__ void ldsm_x2t(uint32_t r[2], uint32_t a) {
    asm volatile("ldmatrix.sync.aligned.m8n8.x2.trans.shared.b16 {%0,%1}, [%2];"
                 : "=r"(r[0]), "=r"(r[1]) : "r"(a));
}
__device__ __forceinline__ void mma_bf16(float c[4], const uint32_t a[4], const uint32_t b[2]) {
    asm volatile("mma.sync.aligned.m16n8k16.row.col.f32.bf16.bf16.f32 "
                 "{%0,%1,%2,%3}, {%4,%5,%6,%7}, {%8,%9}, {%0,%1,%2,%3};"
                 : "+f"(c[0]), "+f"(c[1]), "+f"(c[2]), "+f"(c[3])
                 : "r"(a[0]), "r"(a[1]), "r"(a[2]), "r"(a[3]), "r"(b[0]), "r"(b[1]));
}

__device__ __forceinline__ float gelu_exact(float v) {
    return 0.5f * v * (1.0f + erff(v * 0.70710678118654752440f));
}

// cp.async (Ampere+, compiles on this toolchain)
__device__ __forceinline__ void cp16(uint32_t dst, const void* src) {
    asm volatile("cp.async.cg.shared.global [%0], [%1], 16;" :: "r"(dst), "l"(src));
}
__device__ __forceinline__ void cp_commit() { asm volatile("cp.async.commit_group;"); }
__device__ __forceinline__ void cp_wait0()  { asm volatile("cp.async.wait_group 0;" ::: "memory"); }
__device__ __forceinline__ void cp_wait1()  { asm volatile("cp.async.wait_group 1;" ::: "memory"); }

// ---------------------------------------------------------------------------
// Elementwise weight split: W fp32 -> Wh, Wl bf16 (same layout)
// ---------------------------------------------------------------------------
__global__ void __launch_bounds__(256)
split_kernel(const float* __restrict__ W,
             __nv_bfloat16* __restrict__ Wh, __nv_bfloat16* __restrict__ Wl)
{
    const size_t i = ((size_t)blockIdx.x * 256 + threadIdx.x) * 4;
    float4 v = *(const float4*)(W + i);
    split_store4(v, Wh + i, Wl + i);
}

// ---------------------------------------------------------------------------
// LayerNorm: writes split bf16 (h, l)
// ---------------------------------------------------------------------------
__global__ void __launch_bounds__(256)
layernorm_kernel(const float* __restrict__ x, const float* __restrict__ w,
                 const float* __restrict__ bsh,
                 __nv_bfloat16* __restrict__ yh, __nv_bfloat16* __restrict__ yl)
{
    __shared__ float s1[256];
    __shared__ float s2[256];
    const int tid = threadIdx.x;
    const size_t row = blockIdx.x;
    const float4* xr = (const float4*)(x + row * Emb);
    float4 v = xr[tid];

    float a = v.x + v.y + v.z + v.w;
    float b = v.x * v.x + v.y * v.y + v.z * v.z + v.w * v.w;
    s1[tid] = a; s2[tid] = b;
    __syncthreads();
    #pragma unroll
    for (int st = 128; st > 0; st >>= 1) {
        if (tid < st) { s1[tid] += s1[tid + st]; s2[tid] += s2[tid + st]; }
        __syncthreads();
    }
    const float mu   = s1[0] * (1.0f / Emb);
    const float var  = s2[0] * (1.0f / Emb) - mu * mu;
    const float rstd = rsqrtf(var + 1e-5f);

    float4 wv = ((const float4*)w)[tid];
    float4 bv = ((const float4*)bsh)[tid];
    float4 o;
    o.x = (v.x - mu) * rstd * wv.x + bv.x;
    o.y = (v.y - mu) * rstd * wv.y + bv.y;
    o.z = (v.z - mu) * rstd * wv.z + bv.z;
    o.w = (v.w - mu) * rstd * wv.w + bv.w;
    split_store4(o, yh + row * Emb + tid * 4, yl + row * Emb + tid * 4);
}

// ---------------------------------------------------------------------------
// bf16-split tensor-core GEMM, pre-split operands + cp.async pipeline.
// C[M,N] = (Ah+Al)[M,K] @ (Bh+Bl)[K,N] + bias (+res) (+GELU)
// 128x128x32 CTA tile, 8 warps (2x4), warp tile 64x32.
// Operands already bf16 h/l in GMEM -> cp.async.cg 16B straight into the
// conflict-free layouts (PA=40: 80B rows, PB=136: 272B rows, both 16B mult).
// Double-buffered, one cp.async group in flight.
// Inner loop: ldmatrix + 3-term mma only (Ah*Bh + Al*Bh + Ah*Bl).
// EPI: 0 = bias (fp32 out); 1 = bias+residual (fp32 out); 2 = bias+GELU (split out)
// ---------------------------------------------------------------------------
#define BM 128
#define BN 128
#define BK 32
#define PA 40
#define PB 136
#define AT_ELE (BM * PA)                       // 5120 bf16 per A tile
#define BT_ELE (BK * PB)                       // 4352 bf16 per B tile
#define BUF_ELE (2 * AT_ELE + 2 * BT_ELE)      // 18944 bf16 per buffer
#define GEMM_SMEM (2 * BUF_ELE * 2)            // 75776 bytes

__device__ __forceinline__ void stage_tile(
    __nv_bfloat16* buf,
    const __nv_bfloat16* __restrict__ Ah_g, const __nv_bfloat16* __restrict__ Al_g,
    const __nv_bfloat16* __restrict__ Bh_g, const __nv_bfloat16* __restrict__ Bl_g,
    int bm, int bn, int k0, int N, int K, int tid)
{
    __nv_bfloat16* Ah = buf;
    __nv_bfloat16* Al = buf + AT_ELE;
    __nv_bfloat16* Bh = buf + 2 * AT_ELE;
    __nv_bfloat16* Bl = buf + 2 * AT_ELE + BT_ELE;
    // A: 128 rows x 4 16B-chunks (32 k), h & l
    #pragma unroll
    for (int i = 0; i < 2; i++) {
        const int u   = tid + 256 * i;
        const int row = u >> 2;
        const int kc  = (u & 3) * 8;
        const size_t go = (size_t)(bm + row) * K + k0 + kc;
        const uint32_t so = cvta_s(Ah + row * PA + kc);
        cp16(so, Ah_g + go);
        cp16(cvta_s(Al + row * PA + kc), Al_g + go);
    }
    // B: 32 rows x 16 16B-chunks (128 n), h & l
    #pragma unroll
    for (int i = 0; i < 2; i++) {
        const int u   = tid + 256 * i;
        const int row = u >> 4;
        const int nc  = (u & 15) * 8;
        const size_t go = (size_t)(k0 + row) * N + bn + nc;
        cp16(cvta_s(Bh + row * PB + nc), Bh_g + go);
        cp16(cvta_s(Bl + row * PB + nc), Bl_g + go);
    }
}

template <int EPI>
__global__ void __launch_bounds__(256)
mma_gemm_kernel(const __nv_bfloat16* __restrict__ Ah_g, const __nv_bfloat16* __restrict__ Al_g,
                const __nv_bfloat16* __restrict__ Bh_g, const __nv_bfloat16* __restrict__ Bl_g,
                const float* __restrict__ bias, const float* __restrict__ res,
                float* __restrict__ Cf,
                __nv_bfloat16* __restrict__ Ch, __nv_bfloat16* __restrict__ Cl,
                int M, int N, int K)
{
    extern __shared__ __nv_bfloat16 smb[];

    const int tid  = threadIdx.x;
    const int lane = tid & 31;
    const int warp = tid >> 5;
    const int wm   = (warp >> 2) * 64;
    const int wn   = (warp & 3) * 32;
    const int g    = lane >> 2;
    const int tg   = lane & 3;

    const int bm = blockIdx.y * BM;
    const int bn = blockIdx.x * BN;

    float acc[4][4][4];
    #pragma unroll
    for (int mi = 0; mi < 4; mi++)
        #pragma unroll
        for (int ni = 0; ni < 4; ni++)
            #pragma unroll
            for (int c = 0; c < 4; c++) acc[mi][ni][c] = 0.0f;

    // ldmatrix lane geometry (R5-proven)
    const int a_r  = (lane & 7) + ((lane >> 3) & 1) * 8;
    const int a_kh = (lane >> 4) * 8;
    const int b_r  = lane & 15;

    const int nk = K >> 5;   // K / 32

    // prologue: stage tile 0
    stage_tile(smb, Ah_g, Al_g, Bh_g, Bl_g, bm, bn, 0, N, K, tid);
    cp_commit();

    for (int t = 0; t < nk; t++) {
        if (t + 1 < nk) {
            stage_tile(smb + ((t + 1) & 1) * BUF_ELE, Ah_g, Al_g, Bh_g, Bl_g,
                       bm, bn, (t + 1) << 5, N, K, tid);
            cp_commit();
            cp_wait1();
        } else {
            cp_wait0();
        }
        __syncthreads();

        const __nv_bfloat16* buf = smb + (t & 1) * BUF_ELE;
        const __nv_bfloat16* Ahb = buf;
        const __nv_bfloat16* Alb = buf + AT_ELE;
        const __nv_bfloat16* Bhb = buf + 2 * AT_ELE;
        const __nv_bfloat16* Blb = buf + 2 * AT_ELE + BT_ELE;

        #pragma unroll
        for (int kk = 0; kk < BK; kk += 16) {
            uint32_t ah[4][4], al[4][4];
            #pragma unroll
            for (int mi = 0; mi < 4; mi++) {
                const int row = wm + mi * 16 + a_r;
                const int kc  = kk + a_kh;
                ldsm_x4(ah[mi], cvta_s(Ahb + row * PA + kc));
                ldsm_x4(al[mi], cvta_s(Alb + row * PA + kc));
            }
            #pragma unroll
            for (int ni = 0; ni < 4; ni++) {
                const int n0 = wn + ni * 8;
                uint32_t bh2[2], bl2[2];
                const int boff = (kk + b_r) * PB + n0;
                ldsm_x2t(bh2, cvta_s(Bhb + boff));
                ldsm_x2t(bl2, cvta_s(Blb + boff));
                #pragma unroll
                for (int mi = 0; mi < 4; mi++) {
                    mma_bf16(acc[mi][ni], ah[mi], bh2);
                    mma_bf16(acc[mi][ni], al[mi], bh2);
                    mma_bf16(acc[mi][ni], ah[mi], bl2);
                }
            }
        }
        __syncthreads();
    }

    // epilogue: c0/c1 at (row g, cols 2tg,2tg+1); c2/c3 at row g+8
    #pragma unroll
    for (int mi = 0; mi < 4; mi++) {
        #pragma unroll
        for (int ni = 0; ni < 4; ni++) {
            const int col = bn + wn + ni * 8 + tg * 2;
            const float bx = bias[col], by = bias[col + 1];
            #pragma unroll
            for (int half = 0; half < 2; half++) {
                const size_t row = (size_t)(bm + wm + mi * 16 + g + half * 8);
                float vx = acc[mi][ni][half * 2 + 0] + bx;
                float vy = acc[mi][ni][half * 2 + 1] + by;
                if (EPI == 1) {
                    float2 rv = *(const float2*)&res[row * N + col];
                    vx += rv.x; vy += rv.y;
                }
                if (EPI == 2) {
                    vx = gelu_exact(vx); vy = gelu_exact(vy);
                    uint32_t h, l;
                    splitpack(vx, vy, h, l);
                    *(uint32_t*)&Ch[row * N + col] = h;
                    *(uint32_t*)&Cl[row * N + col] = l;
                } else {
                    *(float2*)&Cf[row * N + col] = make_float2(vx, vy);
                }
            }
        }
    }
}

// ---------------------------------------------------------------------------
// Tensor-core flash attention (bf16 split, FA2-style register softmax).
// Same as R5 (passed); finalize writes split bf16 ctx (h, l).
// ---------------------------------------------------------------------------
#define PQ 72
#define ATTN_SMEM ((2 * 128 * PQ + 4 * 64 * PQ) * 2)  // 73728 bytes

__global__ void __launch_bounds__(256)
flash_attn_kernel(const float* __restrict__ Q, const float* __restrict__ K,
                  const float* __restrict__ V,
                  __nv_bfloat16* __restrict__ Oh, __nv_bfloat16* __restrict__ Ol)
{
    extern __shared__ __nv_bfloat16 sb[];
    __nv_bfloat16* Qh = sb;
    __nv_bfloat16* Ql = sb + 128 * PQ;
    __nv_bfloat16* Kh = sb + 2 * 128 * PQ;
    __nv_bfloat16* Kl = Kh + 64 * PQ;
    __nv_bfloat16* Vh = Kl + 64 * PQ;
    __nv_bfloat16* Vl = Vh + 64 * PQ;

    const int tid  = threadIdx.x;
    const int lane = tid & 31;
    const int warp = tid >> 5;
    const int g    = lane >> 2;
    const int tg   = lane & 3;

    const int bh = blockIdx.y;
    const int b = bh >> 4, h = bh & 15;
    const int q0 = blockIdx.x << 7;
    const size_t base = (size_t)b * Lseq * Emb + (size_t)h * DHd;

    #pragma unroll
    for (int i = 0; i < 8; i++) {
        const int idx = tid + 256 * i;
        const int r = idx >> 4, c = (idx & 15) * 4;
        float4 qv = *(const float4*)&Q[base + (size_t)(q0 + r) * Emb + c];
        qv.x *= 8.0f; qv.y *= 8.0f; qv.z *= 8.0f; qv.w *= 8.0f;
        split_store4(qv, Qh + r * PQ + c, Ql + r * PQ + c);
    }
    __syncthreads();

    const int a_r  = (lane & 7) + ((lane >> 3) & 1) * 8;
    const int a_kh = (lane >> 4) * 8;
    uint32_t qfh[4][4], qfl[4][4];
    {
        const int row = warp * 16 + a_r;
        #pragma unroll
        for (int ks = 0; ks < 4; ks++) {
            const int kc = 16 * ks + a_kh;
            ldsm_x4(qfh[ks], cvta_s(Qh + row * PQ + kc));
            ldsm_x4(qfl[ks], cvta_s(Ql + row * PQ + kc));
        }
    }

    float oacc[8][4];
    #pragma unroll
    for (int nj = 0; nj < 8; nj++)
        #pragma unroll
        for (int c = 0; c < 4; c++) oacc[nj][c] = 0.0f;
    float mA = -1e30f, mB = -1e30f, lA = 0.0f, lB = 0.0f;

    for (int kb = 0; kb < Lseq / 64; kb++) {
        const int c0 = kb << 6;
        #pragma unroll
        for (int i = 0; i < 4; i++) {
            const int idx = tid + 256 * i;
            const int r = idx >> 4, c = (idx & 15) * 4;
            float4 kv = *(const float4*)&K[base + (size_t)(c0 + r) * Emb + c];
            float4 vv = *(const float4*)&V[base + (size_t)(c0 + r) * Emb + c];
            split_store4(kv, Kh + r * PQ + c, Kl + r * PQ + c);
            split_store4(vv, Vh + r * PQ + c, Vl + r * PQ + c);
        }
        __syncthreads();

        float sacc[8][4];
        #pragma unroll
        for (int ni = 0; ni < 8; ni++)
            #pragma unroll
            for (int c = 0; c < 4; c++) sacc[ni][c] = 0.0f;

        const int qk_row = lane & 7;
        const int qk_kh  = ((lane >> 3) & 1) * 8;
        #pragma unroll
        for (int ks = 0; ks < 4; ks++) {
            #pragma unroll
            for (int ni = 0; ni < 8; ni++) {
                const int n0 = ni * 8;
                uint32_t kh2[2], kl2[2];
                const int koff = (n0 + qk_row) * PQ + 16 * ks + qk_kh;
                ldsm_x2(kh2, cvta_s(Kh + koff));
                ldsm_x2(kl2, cvta_s(Kl + koff));
                mma_bf16(sacc[ni], qfh[ks], kh2);
                mma_bf16(sacc[ni], qfl[ks], kh2);
                mma_bf16(sacc[ni], qfh[ks], kl2);
            }
        }

        float tA = -1e30f, tB = -1e30f;
        #pragma unroll
        for (int ni = 0; ni < 8; ni++) {
            tA = fmaxf(tA, fmaxf(sacc[ni][0], sacc[ni][1]));
            tB = fmaxf(tB, fmaxf(sacc[ni][2], sacc[ni][3]));
        }
        tA = fmaxf(tA, __shfl_xor_sync(0xffffffffu, tA, 1));
        tA = fmaxf(tA, __shfl_xor_sync(0xffffffffu, tA, 2));
        tB = fmaxf(tB, __shfl_xor_sync(0xffffffffu, tB, 1));
        tB = fmaxf(tB, __shfl_xor_sync(0xffffffffu, tB, 2));

        const float mAn = fmaxf(mA, tA), mBn = fmaxf(mB, tB);
        const float aA = __expf(mA - mAn), aB = __expf(mB - mBn);
        mA = mAn; mB = mBn;

        float sA = 0.0f, sB = 0.0f;
        #pragma unroll
        for (int ni = 0; ni < 8; ni++) {
            float p0 = __expf(sacc[ni][0] - mAn);
            float p1 = __expf(sacc[ni][1] - mAn);
            float p2 = __expf(sacc[ni][2] - mBn);
            float p3 = __expf(sacc[ni][3] - mBn);
            sacc[ni][0] = p0; sacc[ni][1] = p1;
            sacc[ni][2] = p2; sacc[ni][3] = p3;
            sA += p0 + p1; sB += p2 + p3;
        }
        sA += __shfl_xor_sync(0xffffffffu, sA, 1);
        sA += __shfl_xor_sync(0xffffffffu, sA, 2);
        sB += __shfl_xor_sync(0xffffffffu, sB, 1);
        sB += __shfl_xor_sync(0xffffffffu, sB, 2);
        lA = lA * aA + sA;
        lB = lB * aB + sB;

        #pragma unroll
        for (int nj = 0; nj < 8; nj++) {
            oacc[nj][0] *= aA; oacc[nj][1] *= aA;
            oacc[nj][2] *= aB; oacc[nj][3] *= aB;
        }

        #pragma unroll
        for (int ks = 0; ks < 4; ks++) {
            uint32_t pfh[4], pfl[4];
            splitpack(sacc[2 * ks][0],     sacc[2 * ks][1],     pfh[0], pfl[0]);
            splitpack(sacc[2 * ks][2],     sacc[2 * ks][3],     pfh[1], pfl[1]);
            splitpack(sacc[2 * ks + 1][0], sacc[2 * ks + 1][1], pfh[2], pfl[2]);
            splitpack(sacc[2 * ks + 1][2], sacc[2 * ks + 1][3], pfh[3], pfl[3]);
            #pragma unroll
            for (int nj = 0; nj < 8; nj++) {
                const int n0 = nj * 8;
                uint32_t vh2[2], vl2[2];
                const int voff = (16 * ks + (lane & 15)) * PQ + n0;
                ldsm_x2t(vh2, cvta_s(Vh + voff));
                ldsm_x2t(vl2, cvta_s(Vl + voff));
                mma_bf16(oacc[nj], pfh, vh2);
                mma_bf16(oacc[nj], pfl, vh2);
                mma_bf16(oacc[nj], pfh, vl2);
            }
        }
        __syncthreads();
    }

    // finalize: ctx = O / l, written as split bf16
    const float iA = 1.0f / lA, iB = 1.0f / lB;
    const int rowA = q0 + warp * 16 + g;
    #pragma unroll
    for (int nj = 0; nj < 8; nj++) {
        const int d = nj * 8 + tg * 2;
        uint32_t hA, lAa, hB, lBb;
        splitpack(oacc[nj][0] * iA, oacc[nj][1] * iA, hA, lAa);
        splitpack(oacc[nj][2] * iB, oacc[nj][3] * iB, hB, lBb);
        const size_t offA = base + (size_t)rowA * Emb + d;
        const size_t offB = base + (size_t)(rowA + 8) * Emb + d;
        *(uint32_t*)&Oh[offA] = hA;  *(uint32_t*)&Ol[offA] = lAa;
        *(uint32_t*)&Oh[offB] = hB;  *(uint32_t*)&Ol[offB] = lBb;
    }
}

// ---------------------------------------------------------------------------
// Launch
// ---------------------------------------------------------------------------
extern "C" void kernel_launch(void* const* d_in, const int* in_sizes, int n_in,
                              void* d_out, int out_size)
{
    const float* x     = (const float*)d_in[0];
    const float* ln1_w = (const float*)d_in[1];
    const float* ln1_b = (const float*)d_in[2];
    const float* wq    = (const float*)d_in[3];
    const float* bq    = (const float*)d_in[4];
    const float* wk    = (const float*)d_in[5];
    const float* bk    = (const float*)d_in[6];
    const float* wv    = (const float*)d_in[7];
    const float* bv    = (const float*)d_in[8];
    const float* wo    = (const float*)d_in[9];
    const float* bo    = (const float*)d_in[10];
    const float* ln2_w = (const float*)d_in[11];
    const float* ln2_b = (const float*)d_in[12];
    const float* wu    = (const float*)d_in[13];
    const float* bu    = (const float*)d_in[14];
    const float* wd    = (const float*)d_in[15];
    const float* bd    = (const float*)d_in[16];
    float* out = (float*)d_out;

    __nv_bfloat16 *xnh, *xnl, *hnh, *hnl, *ctxh, *ctxl, *uph, *upl;
    __nv_bfloat16 *wqh, *wql, *wkh, *wkl, *wvh, *wvl, *woh, *wol, *wuh, *wul, *wdh, *wdl;
    float *q, *k, *v, *hidden;
    cudaGetSymbolAddress((void**)&xnh,  g_xn_h);  cudaGetSymbolAddress((void**)&xnl,  g_xn_l);
    cudaGetSymbolAddress((void**)&hnh,  g_hn_h);  cudaGetSymbolAddress((void**)&hnl,  g_hn_l);
    cudaGetSymbolAddress((void**)&ctxh, g_ctx_h); cudaGetSymbolAddress((void**)&ctxl, g_ctx_l);
    cudaGetSymbolAddress((void**)&uph,  g_up_h);  cudaGetSymbolAddress((void**)&upl,  g_up_l);
    cudaGetSymbolAddress((void**)&q, g_q);        cudaGetSymbolAddress((void**)&k, g_k);
    cudaGetSymbolAddress((void**)&v, g_v);        cudaGetSymbolAddress((void**)&hidden, g_hidden);
    cudaGetSymbolAddress((void**)&wqh, g_wq_h);   cudaGetSymbolAddress((void**)&wql, g_wq_l);
    cudaGetSymbolAddress((void**)&wkh, g_wk_h);   cudaGetSymbolAddress((void**)&wkl, g_wk_l);
    cudaGetSymbolAddress((void**)&wvh, g_wv_h);   cudaGetSymbolAddress((void**)&wvl, g_wv_l);
    cudaGetSymbolAddress((void**)&woh, g_wo_h);   cudaGetSymbolAddress((void**)&wol, g_wo_l);
    cudaGetSymbolAddress((void**)&wuh, g_wu_h);   cudaGetSymbolAddress((void**)&wul, g_wu_l);
    cudaGetSymbolAddress((void**)&wdh, g_wd_h);   cudaGetSymbolAddress((void**)&wdl, g_wd_l);

    cudaFuncSetAttribute(mma_gemm_kernel<0>, cudaFuncAttributeMaxDynamicSharedMemorySize, GEMM_SMEM);
    cudaFuncSetAttribute(mma_gemm_kernel<1>, cudaFuncAttributeMaxDynamicSharedMemorySize, GEMM_SMEM);
    cudaFuncSetAttribute(mma_gemm_kernel<2>, cudaFuncAttributeMaxDynamicSharedMemorySize, GEMM_SMEM);
    cudaFuncSetAttribute(flash_attn_kernel, cudaFuncAttributeMaxDynamicSharedMemorySize, ATTN_SMEM);

    // 0) split weights (same [K,N] layout, bf16 h/l)
    split_kernel<<<(Emb * Emb) / 1024, 256>>>(wq, wqh, wql);
    split_kernel<<<(Emb * Emb) / 1024, 256>>>(wk, wkh, wkl);
    split_kernel<<<(Emb * Emb) / 1024, 256>>>(wv, wvh, wvl);
    split_kernel<<<(Emb * Emb) / 1024, 256>>>(wo, woh, wol);
    split_kernel<<<(Emb * FFd) / 1024, 256>>>(wu, wuh, wul);
    split_kernel<<<(FFd * Emb) / 1024, 256>>>(wd, wdh, wdl);

    const dim3 gE(Emb / 128, ROWS / 128);   // (8, 32)
    const dim3 gF(FFd / 128, ROWS / 128);   // (32, 32)

    // 1) LN1 -> split xn
    layernorm_kernel<<<ROWS, 256>>>(x, ln1_w, ln1_b, xnh, xnl);
    // 2) Q, K, V projections
    mma_gemm_kernel<0><<<gE, 256, GEMM_SMEM>>>(xnh, xnl, wqh, wql, bq, nullptr, q, nullptr, nullptr, ROWS, Emb, Emb);
    mma_gemm_kernel<0><<<gE, 256, GEMM_SMEM>>>(xnh, xnl, wkh, wkl, bk, nullptr, k, nullptr, nullptr, ROWS, Emb, Emb);
    mma_gemm_kernel<0><<<gE, 256, GEMM_SMEM>>>(xnh, xnl, wvh, wvl, bv, nullptr, v, nullptr, nullptr, ROWS, Emb, Emb);
    // 3) Flash attention -> split ctx
    flash_attn_kernel<<<dim3(Lseq / 128, Bb * NH), 256, ATTN_SMEM>>>(q, k, v, ctxh, ctxl);
    // 4) O projection + residual -> hidden (fp32)
    mma_gemm_kernel<1><<<gE, 256, GEMM_SMEM>>>(ctxh, ctxl, woh, wol, bo, x, hidden, nullptr, nullptr, ROWS, Emb, Emb);
    // 5) LN2 -> split hn
    layernorm_kernel<<<ROWS, 256>>>(hidden, ln2_w, ln2_b, hnh, hnl);
    // 6) FFN up + GELU -> split up
    mma_gemm_kernel<2><<<gF, 256, GEMM_SMEM>>>(hnh, hnl, wuh, wul, bu, nullptr, nullptr, uph, upl, ROWS, FFd, Emb);
    // 7) FFN down + bias + residual -> out (fp32)
    mma_gemm_kernel<1><<<gE, 256, GEMM_SMEM>>>(uph, upl, wdh, wdl, bd, hidden, out, nullptr, nullptr, ROWS, Emb, FFd);
}